// round 5
// baseline (speedup 1.0000x reference)
#include <cuda_runtime.h>

// PrefixSumCounts: counts[b,s] = #{t <= s : x[b,t] == x[b,s]}
// B=4, S=4096, V=32000 (fixed by this problem instance).
//
// TWO kernels; the graph-node boundary is the grid barrier (no device-side
// spin barrier, no sync state, no reset bookkeeping).
//
// Kernel A (64 blocks = B*CC chunks of 256):
//   - within-chunk inclusive rank: int4-vectorized LDS scan over earlier
//     warps + __match_any_sync within warp
//   - per-chunk compact hash (1024 slots, alpha<=0.25) of value->count,
//     one insert per warp-distinct value
//   - dump ALL slots packed ((v+1)<<9 | cnt) -> table fully overwritten
//     each launch (no pre-zero needed, L2-resident for kernel B)
//   - out[pos] = rank + 1
//
// Kernel B (64 blocks):
//   - breadth-first batched probing of <=15 earlier-chunk tables: each round
//     issues up to 15 INDEPENDENT L2 loads (MLP), resolves, repeats
//   - out[pos] += base

#define BB 4
#define SS 4096
#define CC 16
#define LL 256              // SS / CC
#define NBLK (BB * CC)      // 64
#define HSLOTS 1024         // per-chunk hash slots, alpha <= 0.25
#define HMASK (HSLOTS - 1)

__device__ int g_tab[NBLK * HSLOTS];   // 256 KB; fully overwritten each launch

__device__ __forceinline__ unsigned int hash_v(int v) {
    return ((unsigned int)v * 2654435761u) >> 22;  // top 10 bits; caller masks
}

__global__ void __launch_bounds__(LL, 1) rank_hash_kernel(
    const int* __restrict__ x, float* __restrict__ out)
{
    __shared__ __align__(16) int xs[LL];
    __shared__ int sval[HSLOTS];
    __shared__ int scnt[HSLOTS];

    const int t = threadIdx.x;
    const int w = t >> 5;
    const int lane = t & 31;
    const int gpos = blockIdx.x * LL + t;   // blockIdx.x = b*CC + c

    // zero SMEM hash (4 slots per thread each array)
#pragma unroll
    for (int i = 0; i < HSLOTS / LL; ++i) {
        sval[t + i * LL] = 0;
        scnt[t + i * LL] = 0;
    }

    const int v = __ldg(&x[gpos]);
    xs[t] = v;
    __syncthreads();

    // ---- rank over earlier warps: vectorized int4 LDS scan ----
    int rank = 0;
    const int lim4 = w << 3;               // (w*32)/4 int4 loads, warp-uniform
    const int4* xs4 = reinterpret_cast<const int4*>(xs);
    for (int j = 0; j < lim4; ++j) {
        const int4 q = xs4[j];
        rank += (q.x == v) + (q.y == v) + (q.z == v) + (q.w == v);
    }
    // in-warp inclusive part
    const unsigned int mmask = __match_any_sync(0xffffffffu, v);
    rank += __popc(mmask & ((1u << lane) - 1u));

    // ---- hash insert: one op per warp-distinct value ----
    const int key = v + 1;
    if (lane == (__ffs(mmask) - 1)) {
        const int wcnt = __popc(mmask);
        unsigned int h = hash_v(v) & HMASK;
        while (true) {
            int old = atomicCAS(&sval[h], 0, key);
            if (old == 0 || old == key) { atomicAdd(&scnt[h], wcnt); break; }
            h = (h + 1) & HMASK;
        }
    }

    out[gpos] = (float)(rank + 1);

    __syncthreads();

    // ---- dump packed table (all slots -> fully overwritten, L2-resident) ----
    int* my_tab = &g_tab[blockIdx.x * HSLOTS];
#pragma unroll
    for (int i = 0; i < HSLOTS / LL; ++i) {
        const int s = t + i * LL;
        const int k = sval[s];
        my_tab[s] = k ? ((k << 9) | scnt[s]) : 0;
    }
}

__global__ void __launch_bounds__(LL, 1) probe_add_kernel(
    const int* __restrict__ x, float* __restrict__ out)
{
    const int c = blockIdx.x & (CC - 1);
    const int b = blockIdx.x >> 4;
    const int t = threadIdx.x;
    const int gpos = blockIdx.x * LL + t;

    const int v = __ldg(&x[gpos]);
    const int key = v + 1;
    const unsigned int h0 = hash_v(v) & HMASK;
    const int* row = &g_tab[(b * CC) * HSLOTS];
    int base = 0;

    bool pend[CC - 1];
    unsigned int hh[CC - 1];
#pragma unroll
    for (int cp = 0; cp < CC - 1; ++cp) { pend[cp] = (cp < c); hh[cp] = h0; }

#pragma unroll
    for (int r = 0; r < 3; ++r) {
        int e[CC - 1];
#pragma unroll
        for (int cp = 0; cp < CC - 1; ++cp) {
            if (pend[cp]) e[cp] = __ldcg(&row[cp * HSLOTS + hh[cp]]);
        }
#pragma unroll
        for (int cp = 0; cp < CC - 1; ++cp) {
            if (pend[cp]) {
                const int ee = e[cp];
                if ((ee >> 9) == key) { base += (ee & 511); pend[cp] = false; }
                else if (ee == 0)     { pend[cp] = false; }
                else                  { hh[cp] = (hh[cp] + 1) & HMASK; }
            }
        }
    }
    // rare fallback for chains unresolved after 3 rounds
#pragma unroll
    for (int cp = 0; cp < CC - 1; ++cp) {
        while (pend[cp]) {
            const int ee = __ldcg(&row[cp * HSLOTS + hh[cp]]);
            if ((ee >> 9) == key) { base += (ee & 511); pend[cp] = false; }
            else if (ee == 0)     { pend[cp] = false; }
            else                  { hh[cp] = (hh[cp] + 1) & HMASK; }
        }
    }

    if (base) out[gpos] += (float)base;
}

extern "C" void kernel_launch(void* const* d_in, const int* in_sizes, int n_in,
                              void* d_out, int out_size) {
    (void)in_sizes; (void)n_in; (void)out_size;
    const int* x = (const int*)d_in[0];
    float* out = (float*)d_out;
    rank_hash_kernel<<<NBLK, LL>>>(x, out);
    probe_add_kernel<<<NBLK, LL>>>(x, out);
}